// round 13
// baseline (speedup 1.0000x reference)
#include <cuda_runtime.h>
#include <cuda_bf16.h>
#include <math.h>

#define NN 512
#define NBATCH 128
#define EPS 1e-8f
#define S_CAP 304
#define PK_CAP ((S_CAP*(S_CAP+1))/2)      /* 46360 floats */
#define PBW_SM (S_CAP-32)                  /* 272 */
#define PK_FULL ((NN*(NN+1))/2)
#define NTB 512
#define NWB 16
#define DYN_B ((PK_CAP + 32*PBW_SM)*4)    /* 220256 B */
#define ZS_SMEM (4*64*65*4)               /* 66560 B */
#define PAD 148

// ---------------- device scratch ----------------
__device__ float g_L[NN*NN];
__device__ float g_Z[NN*NN];
__device__ float g_M[2][64*64];            // double-buffered inverse of diag block
__device__ float g_zpart[8];
__device__ float g_bres[NBATCH];
__device__ __align__(16) float g_fbA[(size_t)NBATCH * PK_FULL];
__device__ __align__(16) float g_fbPB[(size_t)NBATCH * 32 * NN];

// =====================================================================
// K1: L = B^T B + eps I ; Z = L + I.
// =====================================================================
__global__ __launch_bounds__(256) void k_gemm(const float* __restrict__ B)
{
    __shared__ float SA[16][64];
    __shared__ float SB[16][64];
    const int tid = threadIdx.x;
    const int tx = tid & 15, ty = tid >> 4;
    const int i0 = blockIdx.y * 64, j0 = blockIdx.x * 64;

    float acc[4][4];
#pragma unroll
    for (int r = 0; r < 4; ++r)
#pragma unroll
        for (int c = 0; c < 4; ++c) acc[r][c] = 0.f;

    for (int kc = 0; kc < NN; kc += 16) {
        for (int e = tid; e < 16*64; e += 256) {
            int kk = e >> 6, ii = e & 63;
            SA[kk][ii] = B[(kc+kk)*NN + i0 + ii];
            SB[kk][ii] = B[(kc+kk)*NN + j0 + ii];
        }
        __syncthreads();
#pragma unroll
        for (int kk = 0; kk < 16; ++kk) {
            float a[4], bb[4];
#pragma unroll
            for (int r = 0; r < 4; ++r) a[r]  = SA[kk][ty*4 + r];
#pragma unroll
            for (int c = 0; c < 4; ++c) bb[c] = SB[kk][tx*4 + c];
#pragma unroll
            for (int r = 0; r < 4; ++r)
#pragma unroll
                for (int c = 0; c < 4; ++c) acc[r][c] += a[r] * bb[c];
        }
        __syncthreads();
    }
#pragma unroll
    for (int r = 0; r < 4; ++r)
#pragma unroll
        for (int c = 0; c < 4; ++c) {
            int gi = i0 + ty*4 + r, gj = j0 + tx*4 + c;
            float v = acc[r][c] + ((gi == gj) ? EPS : 0.f);
            g_L[gi*NN + gj] = v;
            g_Z[gi*NN + gj] = v + ((gi == gj) ? 1.f : 0.f);
        }
}

// =====================================================================
// Per-batch blocked Cholesky (nb=32), 512 threads. (unchanged)
// =====================================================================
__global__ __launch_bounds__(NTB) void k_batch(const int* __restrict__ x)
{
    extern __shared__ float dynsm[];
    __shared__ int   sidx[NN];
    __shared__ short spos[NN];
    __shared__ unsigned char sact[NN];
    __shared__ float s_inv[32];
    __shared__ int   s_rbD[32];
    __shared__ int   s_sh;

    const int b = blockIdx.x;
    const int tid = threadIdx.x, warp = tid >> 5, lane = tid & 31;

    if (tid < 32) {
        int cnt = 0;
        for (int base = 0; base < NN; base += 32) {
            int g = base + lane;
            int v = (x[b*NN + g] != 0);
            unsigned m = __ballot_sync(0xffffffffu, v);
            int p = cnt + __popc(m & ((1u << lane) - 1u));
            if (v) sidx[p] = g;
            spos[g] = (short)p;
            sact[g] = (unsigned char)v;
            cnt += __popc(m);
        }
        if (lane == 0) s_sh = cnt;
    }
    __syncthreads();
    const int s = s_sh;
    const bool fits = (s <= S_CAP);
    float* A  = fits ? dynsm            : &g_fbA [(size_t)b * PK_FULL];
    float* PB = fits ? (dynsm + PK_CAP) : &g_fbPB[(size_t)b * 32 * NN];
    const int pbw = fits ? PBW_SM : NN;

    for (int i = warp; i < s; i += NWB) {
        const float* Lrow = &g_L[sidx[i] * NN];
        const int rb = (i * (i + 1)) >> 1;
        const int glim = sidx[i] + 1;
        for (int g = lane; g < glim; g += 32) {
            float v = Lrow[g];
            if (sact[g]) A[rb + spos[g]] = v;
        }
    }
    __syncthreads();

    float lsum = 0.f;
    for (int j0 = 0; j0 < s; j0 += 32) {
        const int nbj = (s - j0 < 32) ? (s - j0) : 32;
        if (tid < nbj)
            s_rbD[tid] = (((j0 + tid) * (j0 + tid + 1)) >> 1) + j0;
        __syncthreads();

        if (warp == 0) {
            const int row = j0 + lane;
            const bool act = (lane < nbj);
            const int rbI = act ? ((row * (row + 1)) >> 1) : 0;
            float v[32];
#pragma unroll
            for (int k = 0; k < 32; ++k)
                v[k] = (act && k <= lane && k < nbj) ? A[rbI + j0 + k] : 0.f;

#pragma unroll
            for (int j = 0; j < 32; ++j) {
                if (j >= nbj) break;
                float dj = __shfl_sync(0xffffffffu, v[j], j);
                float d = sqrtf(dj);
                float inv = 1.f / d;
                if (lane == j) { v[j] = d; s_inv[j] = inv; }
                else if (lane > j) v[j] *= inv;
                float cj = (lane > j) ? v[j] : 0.f;
#pragma unroll
                for (int k = j + 1; k < 32; ++k) {
                    float cjk = __shfl_sync(0xffffffffu, cj, k);
                    v[k] -= cj * cjk;
                }
                if (lane == 0) lsum += logf(d);
            }
#pragma unroll
            for (int k = 0; k < 32; ++k)
                if (act && k <= lane && k < nbj) A[rbI + j0 + k] = v[k];
        }
        __syncthreads();

        const int j1 = j0 + 32;
        if (j1 >= s) break;
        const int nrows = s - j1;

        for (int i = j1 + tid; i < s; i += NTB) {
            const int rbI = (i * (i + 1)) >> 1;
            float v[32];
#pragma unroll
            for (int j = 0; j < 32; ++j) v[j] = A[rbI + j0 + j];
#pragma unroll
            for (int j = 0; j < 32; ++j) {
                float acc0 = v[j], acc1 = 0.f;
                const float* dr = &A[s_rbD[j]];
#pragma unroll
                for (int m = 0; m + 1 < j; m += 2) {
                    acc0 -= v[m]   * dr[m];
                    acc1 -= v[m+1] * dr[m+1];
                }
                if (j & 1) acc0 -= v[j-1] * dr[j-1];
                v[j] = (acc0 + acc1) * s_inv[j];
            }
            const int col = i - j1;
#pragma unroll
            for (int j = 0; j < 32; ++j) PB[j * pbw + col] = v[j];
        }
        __syncthreads();

        const int RT = (nrows + 7) >> 3;
        for (int ti = warp; ti < RT; ti += NWB) {
            const int ar = 8 * ti;
            const int ktmax = 2 * ti + 2;
            for (int kt = lane; kt < ktmax; kt += 32) {
                const int bc = 4 * kt;
                float acc[8][4];
#pragma unroll
                for (int qr = 0; qr < 8; ++qr)
#pragma unroll
                    for (int qc = 0; qc < 4; ++qc) acc[qr][qc] = 0.f;
#pragma unroll
                for (int j = 0; j < 32; ++j) {
                    const float* pr = &PB[j * pbw];
                    float4 a0 = *(const float4*)&pr[ar];
                    float4 a1 = *(const float4*)&pr[ar + 4];
                    float4 bv = *(const float4*)&pr[bc];
                    float av[8] = {a0.x,a0.y,a0.z,a0.w,a1.x,a1.y,a1.z,a1.w};
                    float bb[4] = {bv.x,bv.y,bv.z,bv.w};
#pragma unroll
                    for (int qr = 0; qr < 8; ++qr)
#pragma unroll
                        for (int qc = 0; qc < 4; ++qc)
                            acc[qr][qc] += av[qr] * bb[qc];
                }
#pragma unroll
                for (int qr = 0; qr < 8; ++qr) {
                    const int r = j1 + ar + qr;
                    if (r < s) {
                        const int rb = (r * (r + 1)) >> 1;
#pragma unroll
                        for (int qc = 0; qc < 4; ++qc) {
                            const int c = j1 + bc + qc;
                            if (c <= r) A[rb + c] -= acc[qr][qc];
                        }
                    }
                }
            }
        }
        __syncthreads();
    }
    if (tid == 0) g_bres[b] = 2.f * lsum;
}

// =====================================================================
// Z helpers
// =====================================================================
// Factor a 64x64 block in smem (ld 65). 512 threads. Returns lsum (tid 0).
__device__ __forceinline__ float factor64_smem(float* D, float* s_dinv,
                                               int tid, int warp, int lane)
{
    float lsum = 0.f;
#pragma unroll
    for (int cb = 0; cb < 64; cb += 32) {
        if (warp == 0) {
            float v[32];
#pragma unroll
            for (int k = 0; k < 32; ++k)
                v[k] = (k <= lane) ? D[(cb + lane)*65 + cb + k] : 0.f;
#pragma unroll
            for (int j = 0; j < 32; ++j) {
                float dj = __shfl_sync(0xffffffffu, v[j], j);
                float d = sqrtf(dj);
                float inv = 1.f / d;
                if (lane == j) { v[j] = d; s_dinv[j] = inv; }
                else if (lane > j) v[j] *= inv;
                float cj = (lane > j) ? v[j] : 0.f;
#pragma unroll
                for (int k = j + 1; k < 32; ++k) {
                    float cjk = __shfl_sync(0xffffffffu, cj, k);
                    v[k] -= cj * cjk;
                }
                if (lane == 0) lsum += logf(d);
            }
#pragma unroll
            for (int k = 0; k < 32; ++k)
                if (k <= lane) D[(cb + lane)*65 + cb + k] = v[k];
        }
        __syncthreads();

        if (cb == 0) {
            if (tid < 32) {
                const int i = 32 + tid;
                float v[32];
#pragma unroll
                for (int j = 0; j < 32; ++j) v[j] = D[i*65 + j];
#pragma unroll
                for (int j = 0; j < 32; ++j) {
                    float acc = v[j];
                    const float* dr = &D[j*65];
#pragma unroll
                    for (int m = 0; m < j; ++m) acc -= v[m] * dr[m];
                    v[j] = acc * s_dinv[j];
                }
#pragma unroll
                for (int j = 0; j < 32; ++j) D[i*65 + j] = v[j];
            }
            __syncthreads();
            {
                const int r  = 32 + (tid >> 4);
                const int c0 = 32 + ((tid & 15) << 1);
                float a0 = 0.f, a1 = 0.f;
#pragma unroll
                for (int k = 0; k < 32; ++k) {
                    float ar = D[r*65 + k];
                    a0 += ar * D[c0*65 + k];
                    a1 += ar * D[(c0+1)*65 + k];
                }
                D[r*65 + c0]     -= a0;
                D[r*65 + c0 + 1] -= a1;
            }
            __syncthreads();
        }
    }
    return lsum;
}

// Invert factored lower-tri 64x64 L (smem ld65) into M (smem ld65).
// T = 32x33 temp. 512 threads. Fully unrolled (no local-mem spill).
__device__ __forceinline__ void invert64(const float* L, float* M, float* T, int tid)
{
    const int warp = tid >> 5, lane = tid & 31;
    for (int e = tid; e < 64*65; e += 512) M[e] = 0.f;
    __syncthreads();

    if (warp < 2) {
        const int base = warp * 32;
        float y[32];
#pragma unroll
        for (int k = 0; k < 32; ++k) {
            float s = (k == lane) ? 1.0f : 0.0f;
#pragma unroll
            for (int m = 0; m < 32; ++m)
                if (m < k) s -= L[(base + k)*65 + base + m] * y[m];
            y[k] = s / L[(base + k)*65 + base + k];
        }
#pragma unroll
        for (int k = 0; k < 32; ++k)
            M[(base + k)*65 + base + lane] = y[k];    // exact zeros above diag
    }
    __syncthreads();

    // T = L21 * M1   (32x32)
    {
        const int r  = tid >> 4;            // 0..31
        const int c2 = (tid & 15) << 1;     // 0,2,..,30
        float t0 = 0.f, t1 = 0.f;
#pragma unroll
        for (int m = 0; m < 32; ++m) {
            float lv = L[(32 + r)*65 + m];
            t0 += lv * M[m*65 + c2];
            t1 += lv * M[m*65 + c2 + 1];
        }
        T[r*33 + c2] = t0; T[r*33 + c2 + 1] = t1;
    }
    __syncthreads();

    // M21 = -M2 * T
    {
        const int r  = tid >> 4;
        const int c2 = (tid & 15) << 1;
        float s0 = 0.f, s1 = 0.f;
#pragma unroll
        for (int m = 0; m < 32; ++m) {
            float mv = M[(32 + r)*65 + 32 + m];
            s0 += mv * T[m*33 + c2];
            s1 += mv * T[m*33 + c2 + 1];
        }
        M[(32 + r)*65 + c2]     = -s0;
        M[(32 + r)*65 + c2 + 1] = -s1;
    }
    __syncthreads();
}

// O = A * M^T   (64x64, all ld 65), 512 threads, 2x4 tiles.
__device__ __forceinline__ void gemm64_ABt(float* O, const float* A, const float* M, int tid)
{
    const int tx = tid & 15, ty = tid >> 4;
    float acc[2][4];
#pragma unroll
    for (int r = 0; r < 2; ++r)
#pragma unroll
        for (int c = 0; c < 4; ++c) acc[r][c] = 0.f;
#pragma unroll
    for (int k = 0; k < 64; ++k) {
        float a[2], bb[4];
#pragma unroll
        for (int r = 0; r < 2; ++r) a[r]  = A[(ty*2 + r)*65 + k];
#pragma unroll
        for (int c = 0; c < 4; ++c) bb[c] = M[(tx*4 + c)*65 + k];
#pragma unroll
        for (int r = 0; r < 2; ++r)
#pragma unroll
            for (int c = 0; c < 4; ++c) acc[r][c] += a[r] * bb[c];
    }
#pragma unroll
    for (int r = 0; r < 2; ++r)
#pragma unroll
        for (int c = 0; c < 4; ++c)
            O[(ty*2 + r)*65 + tx*4 + c] = acc[r][c];
}

// =====================================================================
// zdiag(p): factor (p,p), write lower + logdet part + inverse -> g_M[p&1]
// =====================================================================
__global__ __launch_bounds__(512) void k_zdiag(int p, int nwork)
{
    if (blockIdx.x >= (unsigned)nwork) return;
    __shared__ float D[64*65];
    __shared__ float M[64*65];
    __shared__ float T[32*33];
    __shared__ float s_dinv[32];
    const int tid = threadIdx.x, warp = tid >> 5, lane = tid & 31;

    for (int e = tid; e < 64*64; e += 512) {
        int r = e >> 6, c = e & 63;
        D[r*65 + c] = g_Z[(64*p + r)*NN + 64*p + c];
    }
    __syncthreads();
    float lsum = factor64_smem(D, s_dinv, tid, warp, lane);
    __syncthreads();
    for (int e = tid; e < 64*64; e += 512) {
        int r = e >> 6, c = e & 63;
        if (c <= r) g_Z[(64*p + r)*NN + 64*p + c] = D[r*65 + c];
    }
    if (tid == 0) g_zpart[p] = 2.f * lsum;
    invert64(D, M, T, tid);
    for (int e = tid; e < 64*64; e += 512)
        g_M[p & 1][e] = M[(e >> 6)*65 + (e & 63)];
}

// =====================================================================
// zstepG(q): CTA l -> block i = q+1+l.
//  CTA l>0 : Xi = (i,q)·M^T -> write (i,q); Xq1 = raw(q+1,q)·M^T;
//            gmem (i,q+1) -= Xi·Xq1^T
//  CTA l=0 : Xq1 = raw(q+1,q)·M^T (NOT written back — nothing reads it);
//            D=(q+1,q+1); D -= Xq1·Xq1^T; factor; write lower+logdet;
//            invert -> g_M[(q+1)&1]
// smem: M | Xi | Xq1 | W  (4 x 64x65); T carved from W tail.
// =====================================================================
__global__ __launch_bounds__(512) void k_zstepG(int q, int nwork)
{
    if (blockIdx.x >= (unsigned)nwork) return;
    extern __shared__ float sm[];
    float* M   = sm;
    float* Xi  = sm + 64*65;
    float* Xq1 = sm + 2*64*65;
    float* W   = sm + 3*64*65;
    __shared__ float s_dinv[32];
    const int tid = threadIdx.x, warp = tid >> 5, lane = tid & 31;
    const int i = q + 1 + blockIdx.x;

    // load inverse + raw (q+1,q)
    for (int e = tid; e < 64*64; e += 512)
        M[(e >> 6)*65 + (e & 63)] = g_M[q & 1][e];
    for (int e = tid; e < 64*64; e += 512) {
        int r = e >> 6, c = e & 63;
        W[r*65 + c] = g_Z[(64*(q+1) + r)*NN + 64*q + c];
    }
    __syncthreads();
    gemm64_ABt(Xq1, W, M, tid);
    __syncthreads();

    if (blockIdx.x > 0) {
        // Xi = raw(i,q)·M^T
        for (int e = tid; e < 64*64; e += 512) {
            int r = e >> 6, c = e & 63;
            W[r*65 + c] = g_Z[(64*i + r)*NN + 64*q + c];
        }
        __syncthreads();
        gemm64_ABt(Xi, W, M, tid);
        __syncthreads();
        // write back solved (i,q)
        for (int e = tid; e < 64*64; e += 512) {
            int r = e >> 6, c = e & 63;
            g_Z[(64*i + r)*NN + 64*q + c] = Xi[r*65 + c];
        }
        // (i,q+1) -= Xi·Xq1^T (direct to gmem; exclusive ownership)
        const int tx = tid & 15, ty = tid >> 4;
        float acc[2][4];
#pragma unroll
        for (int r = 0; r < 2; ++r)
#pragma unroll
            for (int c = 0; c < 4; ++c) acc[r][c] = 0.f;
#pragma unroll
        for (int k = 0; k < 64; ++k) {
            float a[2], bb[4];
#pragma unroll
            for (int r = 0; r < 2; ++r) a[r]  = Xi[(ty*2 + r)*65 + k];
#pragma unroll
            for (int c = 0; c < 4; ++c) bb[c] = Xq1[(tx*4 + c)*65 + k];
#pragma unroll
            for (int r = 0; r < 2; ++r)
#pragma unroll
                for (int c = 0; c < 4; ++c) acc[r][c] += a[r] * bb[c];
        }
#pragma unroll
        for (int r = 0; r < 2; ++r)
#pragma unroll
            for (int c = 0; c < 4; ++c)
                g_Z[(64*i + ty*2 + r)*NN + 64*(q+1) + tx*4 + c] -= acc[r][c];
    } else {
        // D = (q+1,q+1) into Xi
        for (int e = tid; e < 64*64; e += 512) {
            int r = e >> 6, c = e & 63;
            Xi[r*65 + c] = g_Z[(64*(q+1) + r)*NN + 64*(q+1) + c];
        }
        __syncthreads();
        // D -= Xq1·Xq1^T (into smem)
        {
            const int tx = tid & 15, ty = tid >> 4;
            float acc[2][4];
#pragma unroll
            for (int r = 0; r < 2; ++r)
#pragma unroll
                for (int c = 0; c < 4; ++c) acc[r][c] = 0.f;
#pragma unroll
            for (int k = 0; k < 64; ++k) {
                float a[2], bb[4];
#pragma unroll
                for (int r = 0; r < 2; ++r) a[r]  = Xq1[(ty*2 + r)*65 + k];
#pragma unroll
                for (int c = 0; c < 4; ++c) bb[c] = Xq1[(tx*4 + c)*65 + k];
#pragma unroll
                for (int r = 0; r < 2; ++r)
#pragma unroll
                    for (int c = 0; c < 4; ++c) acc[r][c] += a[r] * bb[c];
            }
#pragma unroll
            for (int r = 0; r < 2; ++r)
#pragma unroll
                for (int c = 0; c < 4; ++c)
                    Xi[(ty*2 + r)*65 + tx*4 + c] -= acc[r][c];
        }
        __syncthreads();
        float lsum = factor64_smem(Xi, s_dinv, tid, warp, lane);
        __syncthreads();
        for (int e = tid; e < 64*64; e += 512) {
            int r = e >> 6, c = e & 63;
            if (c <= r) g_Z[(64*(q+1) + r)*NN + 64*(q+1) + c] = Xi[r*65 + c];
        }
        if (tid == 0) g_zpart[q+1] = 2.f * lsum;
        invert64(Xi, M, W /* temp 32x33 fits */, tid);
        for (int e = tid; e < 64*64; e += 512)
            g_M[(q+1) & 1][e] = M[(e >> 6)*65 + (e & 63)];
    }
}

// =====================================================================
// zrestN(j): apply panel j to column j+2 only (on s2)
// =====================================================================
__global__ __launch_bounds__(256) void k_zrestN(int j, int nwork)
{
    if (blockIdx.x >= (unsigned)nwork) return;
    __shared__ float As[64][65];
    __shared__ float Bs[64][65];
    const int bj = j + 2;
    const int bi = bj + blockIdx.x;
    const int tid = threadIdx.x;
    const int tx = tid & 15, ty = tid >> 4;

    for (int e = tid; e < 64*64; e += 256) {
        int r = e >> 6, k = e & 63;
        As[r][k] = g_Z[(64*bi + r)*NN + 64*j + k];
    }
    for (int e = tid; e < 64*64; e += 256) {
        int r = e >> 6, k = e & 63;
        Bs[r][k] = g_Z[(64*bj + r)*NN + 64*j + k];
    }
    __syncthreads();

    float acc[4][4];
#pragma unroll
    for (int r = 0; r < 4; ++r)
#pragma unroll
        for (int c = 0; c < 4; ++c) acc[r][c] = 0.f;
    for (int k = 0; k < 64; ++k) {
        float a[4], bb[4];
#pragma unroll
        for (int r = 0; r < 4; ++r) a[r]  = As[ty*4 + r][k];
#pragma unroll
        for (int c = 0; c < 4; ++c) bb[c] = Bs[tx*4 + c][k];
#pragma unroll
        for (int r = 0; r < 4; ++r)
#pragma unroll
            for (int c = 0; c < 4; ++c) acc[r][c] += a[r] * bb[c];
    }
#pragma unroll
    for (int r = 0; r < 4; ++r)
#pragma unroll
        for (int c = 0; c < 4; ++c)
            g_Z[(64*bi + ty*4 + r)*NN + 64*bj + tx*4 + c] -= acc[r][c];
}

// =====================================================================
// zfar(j): apply panel j to columns j+3..7 (on s3)
// =====================================================================
__global__ __launch_bounds__(256) void k_zfar(int j)
{
    __shared__ float As[64][65];
    __shared__ float Bs[64][65];
    int l = blockIdx.x, bi = 0, bj = 0;
    for (int c = j + 3; c <= 7; ++c) {
        int cnt = 8 - c;
        if (l < cnt) { bj = c; bi = c + l; break; }
        l -= cnt;
    }
    const int tid = threadIdx.x;
    const int tx = tid & 15, ty = tid >> 4;

    for (int e = tid; e < 64*64; e += 256) {
        int r = e >> 6, k = e & 63;
        As[r][k] = g_Z[(64*bi + r)*NN + 64*j + k];
    }
    for (int e = tid; e < 64*64; e += 256) {
        int r = e >> 6, k = e & 63;
        Bs[r][k] = g_Z[(64*bj + r)*NN + 64*j + k];
    }
    __syncthreads();

    float acc[4][4];
#pragma unroll
    for (int r = 0; r < 4; ++r)
#pragma unroll
        for (int c = 0; c < 4; ++c) acc[r][c] = 0.f;
    for (int k = 0; k < 64; ++k) {
        float a[4], bb[4];
#pragma unroll
        for (int r = 0; r < 4; ++r) a[r]  = As[ty*4 + r][k];
#pragma unroll
        for (int c = 0; c < 4; ++c) bb[c] = Bs[tx*4 + c][k];
#pragma unroll
        for (int r = 0; r < 4; ++r)
#pragma unroll
            for (int c = 0; c < 4; ++c) acc[r][c] += a[r] * bb[c];
    }
#pragma unroll
    for (int r = 0; r < 4; ++r)
#pragma unroll
        for (int c = 0; c < 4; ++c)
            g_Z[(64*bi + ty*4 + r)*NN + 64*bj + tx*4 + c] -= acc[r][c];
}

// =====================================================================
__global__ void k_combine(float* __restrict__ out)
{
    __shared__ float z;
    if (threadIdx.x == 0) {
        float t = 0.f;
        for (int p = 0; p < 8; ++p) t += g_zpart[p];
        z = t;
    }
    __syncthreads();
    if (threadIdx.x < NBATCH)
        out[threadIdx.x] = g_bres[threadIdx.x] - z;
}

// =====================================================================
extern "C" void kernel_launch(void* const* d_in, const int* in_sizes, int n_in,
                              void* d_out, int out_size)
{
    const int* x = (const int*)d_in[0];
    const float* Bm = (const float*)d_in[1];
    if (in_sizes[0] == NN*NN && in_sizes[1] == NBATCH*NN) {
        x  = (const int*)d_in[1];
        Bm = (const float*)d_in[0];
    }
    float* out = (float*)d_out;

    cudaFuncSetAttribute(k_batch,  cudaFuncAttributeMaxDynamicSharedMemorySize, DYN_B);
    cudaFuncSetAttribute(k_zstepG, cudaFuncAttributeMaxDynamicSharedMemorySize, ZS_SMEM);

    cudaStream_t s2, s3;
    cudaStreamCreateWithFlags(&s2, cudaStreamNonBlocking);
    cudaStreamCreateWithFlags(&s3, cudaStreamNonBlocking);
    cudaEvent_t eg, e2, es[5], efar[5];
    cudaEventCreateWithFlags(&eg, cudaEventDisableTiming);
    cudaEventCreateWithFlags(&e2, cudaEventDisableTiming);
    for (int i = 0; i < 5; ++i) {
        cudaEventCreateWithFlags(&es[i], cudaEventDisableTiming);
        cudaEventCreateWithFlags(&efar[i], cudaEventDisableTiming);
    }

    k_gemm<<<dim3(8,8), 256>>>(Bm);                              // #1 (main)
    cudaEventRecord(eg, 0);
    k_batch<<<NBATCH, NTB, DYN_B>>>(x);                          // #2 (main)

    cudaStreamWaitEvent(s2, eg, 0);
    k_zdiag<<<PAD, 512, 0, s2>>>(0, 1);                          // #3 (s2)
    k_zstepG<<<PAD, 512, ZS_SMEM, s2>>>(0, 7);                   // #4 (s2) <- profiled
    cudaEventRecord(es[0], s2);
    cudaStreamWaitEvent(s3, es[0], 0);
    k_zfar<<<15, 256, 0, s3>>>(0);
    cudaEventRecord(efar[0], s3);

    for (int m = 1; m <= 6; ++m) {
        if (m >= 2) cudaStreamWaitEvent(s2, efar[m-2], 0);       // order col writers
        k_zrestN<<<PAD, 256, 0, s2>>>(m - 1, 7 - m);
        k_zstepG<<<PAD, 512, ZS_SMEM, s2>>>(m, 7 - m);
        if (m <= 4) {
            cudaEventRecord(es[m], s2);
            cudaStreamWaitEvent(s3, es[m], 0);
            k_zfar<<<(5 - m) * (6 - m) / 2, 256, 0, s3>>>(m);
            cudaEventRecord(efar[m], s3);
        }
    }
    cudaEventRecord(e2, s2);
    cudaStreamWaitEvent(0, e2, 0);
    k_combine<<<1, 128>>>(out);                                  // last (main)

    cudaStreamCaptureStatus st = cudaStreamCaptureStatusNone;
    cudaStreamIsCapturing(0, &st);
    if (st == cudaStreamCaptureStatusNone) {
        cudaEventDestroy(eg); cudaEventDestroy(e2);
        for (int i = 0; i < 5; ++i) { cudaEventDestroy(es[i]); cudaEventDestroy(efar[i]); }
        cudaStreamDestroy(s2); cudaStreamDestroy(s3);
    }
}

// round 14
// speedup vs baseline: 1.1418x; 1.1418x over previous
#include <cuda_runtime.h>
#include <cuda_bf16.h>
#include <math.h>

#define NN 512
#define NBATCH 128
#define EPS 1e-8f
#define S_CAP 304
#define PK_CAP ((S_CAP*(S_CAP+1))/2)      /* 46360 floats */
#define PBW_SM (S_CAP-32)                  /* 272 */
#define PK_FULL ((NN*(NN+1))/2)
#define NTB 512
#define NWB 16
#define NT 512                             /* zpanelN threads */
#define NW 16
#define SN_T 512                           /* zsn threads */
#define DYN_B ((PK_CAP + 32*PBW_SM)*4)    /* 220256 B */

// ---------------- device scratch ----------------
__device__ float g_L[NN*NN];
__device__ float g_Z[NN*NN];
__device__ float g_zpart[8];
__device__ float g_bres[NBATCH];
__device__ __align__(16) float g_fbA[(size_t)NBATCH * PK_FULL];
__device__ __align__(16) float g_fbPB[(size_t)NBATCH * 32 * NN];

// =====================================================================
// K1: L = B^T B + eps I ; Z = L + I.
// =====================================================================
__global__ __launch_bounds__(256) void k_gemm(const float* __restrict__ B)
{
    __shared__ float SA[16][64];
    __shared__ float SB[16][64];
    const int tid = threadIdx.x;
    const int tx = tid & 15, ty = tid >> 4;
    const int i0 = blockIdx.y * 64, j0 = blockIdx.x * 64;

    float acc[4][4];
#pragma unroll
    for (int r = 0; r < 4; ++r)
#pragma unroll
        for (int c = 0; c < 4; ++c) acc[r][c] = 0.f;

    for (int kc = 0; kc < NN; kc += 16) {
        for (int e = tid; e < 16*64; e += 256) {
            int kk = e >> 6, ii = e & 63;
            SA[kk][ii] = B[(kc+kk)*NN + i0 + ii];
            SB[kk][ii] = B[(kc+kk)*NN + j0 + ii];
        }
        __syncthreads();
#pragma unroll
        for (int kk = 0; kk < 16; ++kk) {
            float a[4], bb[4];
#pragma unroll
            for (int r = 0; r < 4; ++r) a[r]  = SA[kk][ty*4 + r];
#pragma unroll
            for (int c = 0; c < 4; ++c) bb[c] = SB[kk][tx*4 + c];
#pragma unroll
            for (int r = 0; r < 4; ++r)
#pragma unroll
                for (int c = 0; c < 4; ++c) acc[r][c] += a[r] * bb[c];
        }
        __syncthreads();
    }
#pragma unroll
    for (int r = 0; r < 4; ++r)
#pragma unroll
        for (int c = 0; c < 4; ++c) {
            int gi = i0 + ty*4 + r, gj = j0 + tx*4 + c;
            float v = acc[r][c] + ((gi == gj) ? EPS : 0.f);
            g_L[gi*NN + gj] = v;
            g_Z[gi*NN + gj] = v + ((gi == gj) ? 1.f : 0.f);
        }
}

// =====================================================================
// Per-batch blocked Cholesky (nb=32), 512 threads. (unchanged from R11)
// =====================================================================
__global__ __launch_bounds__(NTB) void k_batch(const int* __restrict__ x)
{
    extern __shared__ float dynsm[];
    __shared__ int   sidx[NN];
    __shared__ short spos[NN];
    __shared__ unsigned char sact[NN];
    __shared__ float s_inv[32];
    __shared__ int   s_rbD[32];
    __shared__ int   s_sh;

    const int b = blockIdx.x;
    const int tid = threadIdx.x, warp = tid >> 5, lane = tid & 31;

    if (tid < 32) {
        int cnt = 0;
        for (int base = 0; base < NN; base += 32) {
            int g = base + lane;
            int v = (x[b*NN + g] != 0);
            unsigned m = __ballot_sync(0xffffffffu, v);
            int p = cnt + __popc(m & ((1u << lane) - 1u));
            if (v) sidx[p] = g;
            spos[g] = (short)p;
            sact[g] = (unsigned char)v;
            cnt += __popc(m);
        }
        if (lane == 0) s_sh = cnt;
    }
    __syncthreads();
    const int s = s_sh;
    const bool fits = (s <= S_CAP);
    float* A  = fits ? dynsm            : &g_fbA [(size_t)b * PK_FULL];
    float* PB = fits ? (dynsm + PK_CAP) : &g_fbPB[(size_t)b * 32 * NN];
    const int pbw = fits ? PBW_SM : NN;

    for (int i = warp; i < s; i += NWB) {
        const float* Lrow = &g_L[sidx[i] * NN];
        const int rb = (i * (i + 1)) >> 1;
        const int glim = sidx[i] + 1;
        for (int g = lane; g < glim; g += 32) {
            float v = Lrow[g];
            if (sact[g]) A[rb + spos[g]] = v;
        }
    }
    __syncthreads();

    float lsum = 0.f;
    for (int j0 = 0; j0 < s; j0 += 32) {
        const int nbj = (s - j0 < 32) ? (s - j0) : 32;
        if (tid < nbj)
            s_rbD[tid] = (((j0 + tid) * (j0 + tid + 1)) >> 1) + j0;
        __syncthreads();

        if (warp == 0) {
            const int row = j0 + lane;
            const bool act = (lane < nbj);
            const int rbI = act ? ((row * (row + 1)) >> 1) : 0;
            float v[32];
#pragma unroll
            for (int k = 0; k < 32; ++k)
                v[k] = (act && k <= lane && k < nbj) ? A[rbI + j0 + k] : 0.f;

#pragma unroll
            for (int j = 0; j < 32; ++j) {
                if (j >= nbj) break;
                float dj = __shfl_sync(0xffffffffu, v[j], j);
                float d = sqrtf(dj);
                float inv = 1.f / d;
                if (lane == j) { v[j] = d; s_inv[j] = inv; }
                else if (lane > j) v[j] *= inv;
                float cj = (lane > j) ? v[j] : 0.f;
#pragma unroll
                for (int k = j + 1; k < 32; ++k) {
                    float cjk = __shfl_sync(0xffffffffu, cj, k);
                    v[k] -= cj * cjk;
                }
                if (lane == 0) lsum += logf(d);
            }
#pragma unroll
            for (int k = 0; k < 32; ++k)
                if (act && k <= lane && k < nbj) A[rbI + j0 + k] = v[k];
        }
        __syncthreads();

        const int j1 = j0 + 32;
        if (j1 >= s) break;
        const int nrows = s - j1;

        for (int i = j1 + tid; i < s; i += NTB) {
            const int rbI = (i * (i + 1)) >> 1;
            float v[32];
#pragma unroll
            for (int j = 0; j < 32; ++j) v[j] = A[rbI + j0 + j];
#pragma unroll
            for (int j = 0; j < 32; ++j) {
                float acc0 = v[j], acc1 = 0.f;
                const float* dr = &A[s_rbD[j]];
#pragma unroll
                for (int m = 0; m + 1 < j; m += 2) {
                    acc0 -= v[m]   * dr[m];
                    acc1 -= v[m+1] * dr[m+1];
                }
                if (j & 1) acc0 -= v[j-1] * dr[j-1];
                v[j] = (acc0 + acc1) * s_inv[j];
            }
            const int col = i - j1;
#pragma unroll
            for (int j = 0; j < 32; ++j) PB[j * pbw + col] = v[j];
        }
        __syncthreads();

        const int RT = (nrows + 7) >> 3;
        for (int ti = warp; ti < RT; ti += NWB) {
            const int ar = 8 * ti;
            const int ktmax = 2 * ti + 2;
            for (int kt = lane; kt < ktmax; kt += 32) {
                const int bc = 4 * kt;
                float acc[8][4];
#pragma unroll
                for (int qr = 0; qr < 8; ++qr)
#pragma unroll
                    for (int qc = 0; qc < 4; ++qc) acc[qr][qc] = 0.f;
#pragma unroll
                for (int j = 0; j < 32; ++j) {
                    const float* pr = &PB[j * pbw];
                    float4 a0 = *(const float4*)&pr[ar];
                    float4 a1 = *(const float4*)&pr[ar + 4];
                    float4 bv = *(const float4*)&pr[bc];
                    float av[8] = {a0.x,a0.y,a0.z,a0.w,a1.x,a1.y,a1.z,a1.w};
                    float bb[4] = {bv.x,bv.y,bv.z,bv.w};
#pragma unroll
                    for (int qr = 0; qr < 8; ++qr)
#pragma unroll
                        for (int qc = 0; qc < 4; ++qc)
                            acc[qr][qc] += av[qr] * bb[qc];
                }
#pragma unroll
                for (int qr = 0; qr < 8; ++qr) {
                    const int r = j1 + ar + qr;
                    if (r < s) {
                        const int rb = (r * (r + 1)) >> 1;
#pragma unroll
                        for (int qc = 0; qc < 4; ++qc) {
                            const int c = j1 + bc + qc;
                            if (c <= r) A[rb + c] -= acc[qr][qc];
                        }
                    }
                }
            }
        }
        __syncthreads();
    }
    if (tid == 0) g_bres[b] = 2.f * lsum;
}

// =====================================================================
// Thin Z panel (R14): factor 64-col panel over rows of blocks p, p+1.
// Phase B replaced by: warp0 inverts the 32x32 diag block (parallel over
// 32 columns), then rows below solve via a parallel GEMM x = a·Minv^T.
// =====================================================================
__global__ __launch_bounds__(NT) void k_zpanelN(int p)
{
    extern __shared__ float T[];              // nr x 65
    __shared__ float s_inv[32];
    __shared__ float Minv[32*33];
    const int nr_full = NN - 64 * p;
    const int nr = (nr_full < 128) ? nr_full : 128;
    const int tid = threadIdx.x, warp = tid >> 5, lane = tid & 31;

    for (int r = warp; r < nr; r += NW) {
        const float* src = &g_Z[(64*p + r)*NN + 64*p];
        float* dst = &T[r*65];
        for (int j = lane; j < 64; j += 32) dst[j] = src[j];
    }
    __syncthreads();

    float lsum = 0.f;
    for (int cb = 0; cb < 64; cb += 32) {
        // ---- Phase A: warp0 factors 32x32 diag block (registers+shfl) ----
        if (warp == 0) {
            float v[32];
#pragma unroll
            for (int k = 0; k < 32; ++k)
                v[k] = (k <= lane) ? T[(cb+lane)*65 + cb + k] : 0.f;
#pragma unroll
            for (int j = 0; j < 32; ++j) {
                float dj = __shfl_sync(0xffffffffu, v[j], j);
                float d = sqrtf(dj);
                float inv = 1.f / d;
                if (lane == j) { v[j] = d; s_inv[j] = inv; }
                else if (lane > j) v[j] *= inv;
                float cj = (lane > j) ? v[j] : 0.f;
#pragma unroll
                for (int k = j + 1; k < 32; ++k) {
                    float cjk = __shfl_sync(0xffffffffu, cj, k);
                    v[k] -= cj * cjk;
                }
                if (lane == 0) lsum += logf(d);
            }
#pragma unroll
            for (int k = 0; k < 32; ++k)
                if (k <= lane) T[(cb+lane)*65 + cb + k] = v[k];
            __syncwarp();

            // ---- invert factored block: lane = column, y in registers ----
            {
                float y[32];
#pragma unroll
                for (int k = 0; k < 32; ++k) {
                    float s = (k == lane) ? 1.0f : 0.0f;
#pragma unroll
                    for (int m = 0; m < 32; ++m)
                        if (m < k) s -= T[(cb + k)*65 + cb + m] * y[m];
                    y[k] = s * s_inv[k];
                }
#pragma unroll
                for (int k = 0; k < 32; ++k)
                    Minv[k*33 + lane] = y[k];   // exact zeros for k < lane
            }
        }
        __syncthreads();

        const int r1 = cb + 32;
        const int nrows = nr - r1;
        // ---- Phase B (GEMM form): rows r1..nr-1, x = a · Minv^T ----
        // 4 threads per row, 8 output cols each. nrows*4 <= 512 (single pass).
        if (tid < nrows * 4) {
            const int i  = r1 + (tid >> 2);
            const int jq = (tid & 3) * 8;
            float a[32];
#pragma unroll
            for (int m = 0; m < 32; ++m) a[m] = T[i*65 + cb + m];
            float xo[8];
#pragma unroll
            for (int jj = 0; jj < 8; ++jj) {
                const float* mr = &Minv[(jq + jj)*33];
                float s0 = 0.f, s1 = 0.f;
#pragma unroll
                for (int m = 0; m < 32; m += 2) {
                    s0 += a[m]   * mr[m];
                    s1 += a[m+1] * mr[m+1];
                }
                xo[jj] = s0 + s1;
            }
            __syncthreads();   // all reads done before any write
#pragma unroll
            for (int jj = 0; jj < 8; ++jj)
                T[i*65 + cb + jq + jj] = xo[jj];
        } else {
            __syncthreads();
        }
        __syncthreads();

        // ---- Phase C (cb==0): rank-32 update of cols 32..63 ----
        if (cb == 0) {
            const int nrows2 = nr - 32;
            const int RT = (nrows2 + 15) >> 4;
            const int sub = lane >> 3;
            const int ktc = lane & 7;
            for (int ti = warp; ti < RT; ti += NW) {
                const int r0 = 32 + ti*16 + sub*4;
                const int c0 = 32 + ktc*4;
                float acc[4][4];
#pragma unroll
                for (int qr = 0; qr < 4; ++qr)
#pragma unroll
                    for (int qc = 0; qc < 4; ++qc) acc[qr][qc] = 0.f;
#pragma unroll
                for (int j = 0; j < 32; ++j) {
                    float a[4], bb[4];
#pragma unroll
                    for (int q = 0; q < 4; ++q) {
                        int r = r0 + q; if (r > nr - 1) r = nr - 1;
                        a[q] = T[r*65 + j];
                    }
#pragma unroll
                    for (int q = 0; q < 4; ++q) bb[q] = T[(c0+q)*65 + j];
#pragma unroll
                    for (int qr = 0; qr < 4; ++qr)
#pragma unroll
                        for (int qc = 0; qc < 4; ++qc)
                            acc[qr][qc] += a[qr] * bb[qc];
                }
#pragma unroll
                for (int qr = 0; qr < 4; ++qr) {
                    const int r = r0 + qr;
#pragma unroll
                    for (int qc = 0; qc < 4; ++qc) {
                        const int c = c0 + qc;
                        if (r < nr && c <= r)
                            T[r*65 + c] -= acc[qr][qc];
                    }
                }
            }
        }
        __syncthreads();
    }

    for (int r = warp; r < nr; r += NW) {
        float* dst = &g_Z[(64*p + r)*NN + 64*p];
        int jmax = (r < 63) ? r : 63;
        for (int j = lane; j <= jmax; j += 32) dst[j] = T[r*65 + j];
    }
    if (tid == 0) g_zpart[p] = 2.f * lsum;
}

// =====================================================================
// zsn(q): unchanged from R11. CTA l -> block i = q+1+l.
// =====================================================================
__global__ __launch_bounds__(SN_T) void k_zsn(int q)
{
    extern __shared__ float sm[];
    float* L11 = sm;
    float* Xq1 = sm + 64*65;
    float* Ai  = sm + 2*64*65;
    __shared__ float s_inv[64];
    const int tid = threadIdx.x;
    const int i = q + 1 + blockIdx.x;

    for (int e = tid; e < 64*64; e += SN_T) {
        int r = e >> 6, c = e & 63;
        L11[r*65 + c] = g_Z[(64*q + r)*NN + 64*q + c];
        Xq1[r*65 + c] = g_Z[(64*(q+1) + r)*NN + 64*q + c];
    }
    if (tid < 64)
        s_inv[tid] = 1.f / g_Z[(64*q + tid)*NN + 64*q + tid];
    if (i > q + 1) {
        for (int e = tid; e < 64*64; e += SN_T) {
            int r = e >> 6, c = e & 63;
            Ai[r*65 + c] = g_Z[(64*i + r)*NN + 64*q + c];
        }
    }
    __syncthreads();

    if (i > q + 1) {
        if (tid < 64) {
            float* row = &Ai[tid*65];
            float x1[32], v[32];
#pragma unroll
            for (int j = 0; j < 32; ++j) x1[j] = row[j];
#pragma unroll
            for (int j = 0; j < 32; ++j) {
                float acc = x1[j];
                const float* dr = &L11[j*65];
#pragma unroll
                for (int m = 0; m < j; ++m) acc -= x1[m] * dr[m];
                x1[j] = acc * s_inv[j];
            }
#pragma unroll
            for (int j = 0; j < 32; ++j) v[j] = row[32 + j];
#pragma unroll
            for (int j = 0; j < 32; ++j) {
                float acc = v[j];
                const float* dr = &L11[(32+j)*65];
#pragma unroll
                for (int m = 0; m < 32; ++m) acc -= x1[m] * dr[m];
#pragma unroll
                for (int m = 0; m < j; ++m) acc -= v[m] * dr[32 + m];
                v[j] = acc * s_inv[32 + j];
            }
#pragma unroll
            for (int j = 0; j < 32; ++j) { row[j] = x1[j]; row[32+j] = v[j]; }
        }
        __syncthreads();
        for (int e = tid; e < 64*64; e += SN_T) {
            int r = e >> 6, c = e & 63;
            g_Z[(64*i + r)*NN + 64*q + c] = Ai[r*65 + c];
        }
    }

    const float* Xi = (i > q + 1) ? Ai : Xq1;
    const int tx = tid & 15;
    const int ty = tid >> 4;
    float acc[2][4];
#pragma unroll
    for (int r = 0; r < 2; ++r)
#pragma unroll
        for (int c = 0; c < 4; ++c) acc[r][c] = 0.f;
#pragma unroll
    for (int k = 0; k < 64; ++k) {
        float a[2], bb[4];
#pragma unroll
        for (int r = 0; r < 2; ++r) a[r]  = Xi[(ty*2 + r)*65 + k];
#pragma unroll
        for (int c = 0; c < 4; ++c) bb[c] = Xq1[(tx*4 + c)*65 + k];
#pragma unroll
        for (int r = 0; r < 2; ++r)
#pragma unroll
            for (int c = 0; c < 4; ++c) acc[r][c] += a[r] * bb[c];
    }
#pragma unroll
    for (int r = 0; r < 2; ++r)
#pragma unroll
        for (int c = 0; c < 4; ++c)
            g_Z[(64*i + ty*2 + r)*NN + 64*(q+1) + tx*4 + c] -= acc[r][c];
}

// =====================================================================
// zrest(j): apply panel j to columns j+2..7 (s3, off critical path)
// =====================================================================
__global__ __launch_bounds__(256) void k_zrest(int q)
{
    __shared__ float As[64][65];
    __shared__ float Bs[64][65];
    int l = blockIdx.x, bi = 0, bj = 0;
    for (int c = q + 2; c <= 7; ++c) {
        int cnt = 8 - c;
        if (l < cnt) { bj = c; bi = c + l; break; }
        l -= cnt;
    }
    const int tid = threadIdx.x;
    const int tx = tid & 15, ty = tid >> 4;

    for (int e = tid; e < 64*64; e += 256) {
        int i = e >> 6, k = e & 63;
        As[i][k] = g_Z[(64*bi + i)*NN + 64*q + k];
    }
    for (int e = tid; e < 64*64; e += 256) {
        int i = e >> 6, k = e & 63;
        Bs[i][k] = g_Z[(64*bj + i)*NN + 64*q + k];
    }
    __syncthreads();

    float acc[4][4];
#pragma unroll
    for (int r = 0; r < 4; ++r)
#pragma unroll
        for (int c = 0; c < 4; ++c) acc[r][c] = 0.f;
    for (int k = 0; k < 64; ++k) {
        float a[4], bb[4];
#pragma unroll
        for (int r = 0; r < 4; ++r) a[r]  = As[ty*4 + r][k];
#pragma unroll
        for (int c = 0; c < 4; ++c) bb[c] = Bs[tx*4 + c][k];
#pragma unroll
        for (int r = 0; r < 4; ++r)
#pragma unroll
            for (int c = 0; c < 4; ++c) acc[r][c] += a[r] * bb[c];
    }
#pragma unroll
    for (int r = 0; r < 4; ++r)
#pragma unroll
        for (int c = 0; c < 4; ++c)
            g_Z[(64*bi + ty*4 + r)*NN + 64*bj + tx*4 + c] -= acc[r][c];
}

// =====================================================================
__global__ void k_combine(float* __restrict__ out)
{
    __shared__ float z;
    if (threadIdx.x == 0) {
        float t = 0.f;
        for (int p = 0; p < 8; ++p) t += g_zpart[p];
        z = t;
    }
    __syncthreads();
    if (threadIdx.x < NBATCH)
        out[threadIdx.x] = g_bres[threadIdx.x] - z;
}

// =====================================================================
extern "C" void kernel_launch(void* const* d_in, const int* in_sizes, int n_in,
                              void* d_out, int out_size)
{
    const int* x = (const int*)d_in[0];
    const float* Bm = (const float*)d_in[1];
    if (in_sizes[0] == NN*NN && in_sizes[1] == NBATCH*NN) {
        x  = (const int*)d_in[1];
        Bm = (const float*)d_in[0];
    }
    float* out = (float*)d_out;

    cudaFuncSetAttribute(k_batch, cudaFuncAttributeMaxDynamicSharedMemorySize, DYN_B);
    cudaFuncSetAttribute(k_zsn,   cudaFuncAttributeMaxDynamicSharedMemorySize, 3*64*65*4);

    cudaStream_t s2, s3;
    cudaStreamCreateWithFlags(&s2, cudaStreamNonBlocking);
    cudaStreamCreateWithFlags(&s3, cudaStreamNonBlocking);
    cudaEvent_t eg, e2, es[6], ezr[6];
    cudaEventCreateWithFlags(&eg, cudaEventDisableTiming);
    cudaEventCreateWithFlags(&e2, cudaEventDisableTiming);
    for (int i = 0; i < 6; ++i) {
        cudaEventCreateWithFlags(&es[i], cudaEventDisableTiming);
        cudaEventCreateWithFlags(&ezr[i], cudaEventDisableTiming);
    }

    auto pn_smem = [](int p) {
        int nr_full = NN - 64*p;
        int nr = (nr_full < 128) ? nr_full : 128;
        return nr * 65 * 4;
    };

    k_gemm<<<dim3(8,8), 256>>>(Bm);                                // #1 (main)
    cudaEventRecord(eg, 0);
    cudaStreamWaitEvent(s2, eg, 0);

    k_zpanelN<<<1, NT, pn_smem(0), s2>>>(0);                       // #2 (s2)
    k_zsn<<<7, SN_T, 3*64*65*4, s2>>>(0);                          // #3 (s2)
    cudaEventRecord(es[0], s2);
    k_zpanelN<<<1, NT, pn_smem(1), s2>>>(1);                       // #4 <- profiled
    k_batch<<<NBATCH, NTB, DYN_B>>>(x);                            // #5 (main)

    cudaStreamWaitEvent(s3, es[0], 0);
    k_zrest<<<21, 256, 0, s3>>>(0);
    cudaEventRecord(ezr[0], s3);

    for (int q = 1; q <= 6; ++q) {
        cudaStreamWaitEvent(s2, ezr[q-1], 0);      // order col-(q+1) writers
        k_zsn<<<7 - q, SN_T, 3*64*65*4, s2>>>(q);
        if (q <= 5) cudaEventRecord(es[q], s2);
        k_zpanelN<<<1, NT, pn_smem(q+1), s2>>>(q + 1);
        if (q <= 5) {
            cudaStreamWaitEvent(s3, es[q], 0);
            int nblk = (6 - q) * (7 - q) / 2;
            k_zrest<<<nblk, 256, 0, s3>>>(q);
            cudaEventRecord(ezr[q], s3);
        }
    }
    cudaEventRecord(e2, s2);
    cudaStreamWaitEvent(0, e2, 0);
    k_combine<<<1, 128>>>(out);                                    // last (main)

    cudaStreamCaptureStatus st = cudaStreamCaptureStatusNone;
    cudaStreamIsCapturing(0, &st);
    if (st == cudaStreamCaptureStatusNone) {
        cudaEventDestroy(eg); cudaEventDestroy(e2);
        for (int i = 0; i < 6; ++i) { cudaEventDestroy(es[i]); cudaEventDestroy(ezr[i]); }
        cudaStreamDestroy(s2); cudaStreamDestroy(s3);
    }
}